// round 4
// baseline (speedup 1.0000x reference)
#include <cuda_runtime.h>
#include <cuda_bf16.h>
#include <math.h>

// Problem constants
#define VOC   32000
#define EDIM  200
#define HDIM  512
#define SLEN  64
#define TLEN  64
#define BATCH 64
#define GATE4 (4*HDIM)
#define HB    (HDIM*BATCH)   // 32768

// ---------------- device scratch (no allocation allowed) ----------------
__device__ float g_h0[2][HB];
__device__ float g_h1[2][HB];
__device__ float g_c0[HB];
__device__ float g_c1[HB];
__device__ unsigned long long g_arg[BATCH];

__device__ __forceinline__ float sigf(float x) { return 1.0f / (1.0f + expf(-x)); }

// ---------------- init: zero states + out[0] ----------------
__global__ void init_kernel(float* __restrict__ out)
{
    int idx = blockIdx.x * blockDim.x + threadIdx.x;
    if (idx < HB) {
        g_h0[0][idx] = 0.f;
        g_h1[0][idx] = 0.f;
        g_c0[idx]    = 0.f;
        g_c1[idx]    = 0.f;
    }
    // zero out[0] : BATCH*VOC floats
    for (int i = idx; i < BATCH * VOC; i += gridDim.x * blockDim.x)
        out[i] = 0.f;
}

// ---------------- one LSTM layer for one time step ----------------
// States stored [H][B]. Block: (64 batch lanes, 4 j rows), grid 128 -> all (b,j).
// Each thread computes all 4 gate dots for its (b,j), then updates c,h.
template <int KX, bool GATHER, int LAYER>
__global__ __launch_bounds__(256) void lstm_step(
    const float* __restrict__ Wih, const float* __restrict__ Whh,
    const float* __restrict__ bih, const float* __restrict__ bhh,
    const float* __restrict__ emb,   // GATHER: embedding table [V][KX]
    const int*   __restrict__ toks,  // encoder: src + t*B
    const int*   __restrict__ target,
    const int*   __restrict__ tfm,
    int step, int dec, int ppo, int resetArg)
{
    const int b = threadIdx.x;                 // 0..63
    const int j = blockIdx.x * 4 + threadIdx.y;

    if (resetArg && blockIdx.x == 0 && threadIdx.y == 0)
        g_arg[b] = 0ull;   // consumed only by a later launch (stream-ordered)

    const float* __restrict__ hprev = (LAYER == 0) ? g_h0[ppo ^ 1] : g_h1[ppo ^ 1];
    float* __restrict__ hout        = (LAYER == 0) ? g_h0[ppo]     : g_h1[ppo];
    float* __restrict__ cst         = (LAYER == 0) ? g_c0          : g_c1;

    float a0 = bih[j]          + bhh[j];
    float a1 = bih[HDIM   + j] + bhh[HDIM   + j];
    float a2 = bih[2*HDIM + j] + bhh[2*HDIM + j];
    float a3 = bih[3*HDIM + j] + bhh[3*HDIM + j];

    const float4* w0 = reinterpret_cast<const float4*>(Wih + (size_t)j * KX);
    const float4* w1 = reinterpret_cast<const float4*>(Wih + (size_t)(HDIM   + j) * KX);
    const float4* w2 = reinterpret_cast<const float4*>(Wih + (size_t)(2*HDIM + j) * KX);
    const float4* w3 = reinterpret_cast<const float4*>(Wih + (size_t)(3*HDIM + j) * KX);

    if constexpr (GATHER) {
        int tok;
        if (!dec) {
            tok = toks[b];
        } else {
            if (step == 0) {
                tok = target[b];
            } else if (tfm[step] > 0) {
                tok = target[step * BATCH + b];
            } else {
                unsigned long long k = g_arg[b];
                tok = (int)(0xFFFFFFFFu - (unsigned)(k & 0xFFFFFFFFull));
            }
        }
        const float4* xr = reinterpret_cast<const float4*>(emb + (size_t)tok * KX);
#pragma unroll 5
        for (int k4 = 0; k4 < KX / 4; k4++) {
            float4 xv = xr[k4];
            float4 A0 = w0[k4], A1 = w1[k4], A2 = w2[k4], A3 = w3[k4];
            a0 += A0.x*xv.x + A0.y*xv.y + A0.z*xv.z + A0.w*xv.w;
            a1 += A1.x*xv.x + A1.y*xv.y + A1.z*xv.z + A1.w*xv.w;
            a2 += A2.x*xv.x + A2.y*xv.y + A2.z*xv.z + A2.w*xv.w;
            a3 += A3.x*xv.x + A3.y*xv.y + A3.z*xv.z + A3.w*xv.w;
        }
    } else {
        const float* __restrict__ xin = g_h0[ppo];  // layer1 input = current h0
#pragma unroll 4
        for (int k4 = 0; k4 < KX / 4; k4++) {
            int k = k4 * 4;
            float x0 = xin[(k+0)*BATCH + b];
            float x1 = xin[(k+1)*BATCH + b];
            float x2 = xin[(k+2)*BATCH + b];
            float x3 = xin[(k+3)*BATCH + b];
            float4 A0 = w0[k4], A1 = w1[k4], A2 = w2[k4], A3 = w3[k4];
            a0 += A0.x*x0 + A0.y*x1 + A0.z*x2 + A0.w*x3;
            a1 += A1.x*x0 + A1.y*x1 + A1.z*x2 + A1.w*x3;
            a2 += A2.x*x0 + A2.y*x1 + A2.z*x2 + A2.w*x3;
            a3 += A3.x*x0 + A3.y*x1 + A3.z*x2 + A3.w*x3;
        }
    }

    // recurrent part, K = HDIM
    const float4* u0 = reinterpret_cast<const float4*>(Whh + (size_t)j * HDIM);
    const float4* u1 = reinterpret_cast<const float4*>(Whh + (size_t)(HDIM   + j) * HDIM);
    const float4* u2 = reinterpret_cast<const float4*>(Whh + (size_t)(2*HDIM + j) * HDIM);
    const float4* u3 = reinterpret_cast<const float4*>(Whh + (size_t)(3*HDIM + j) * HDIM);
#pragma unroll 4
    for (int k4 = 0; k4 < HDIM / 4; k4++) {
        int k = k4 * 4;
        float h0v = hprev[(k+0)*BATCH + b];
        float h1v = hprev[(k+1)*BATCH + b];
        float h2v = hprev[(k+2)*BATCH + b];
        float h3v = hprev[(k+3)*BATCH + b];
        float4 U0 = u0[k4], U1 = u1[k4], U2 = u2[k4], U3 = u3[k4];
        a0 += U0.x*h0v + U0.y*h1v + U0.z*h2v + U0.w*h3v;
        a1 += U1.x*h0v + U1.y*h1v + U1.z*h2v + U1.w*h3v;
        a2 += U2.x*h0v + U2.y*h1v + U2.z*h2v + U2.w*h3v;
        a3 += U3.x*h0v + U3.y*h1v + U3.z*h2v + U3.w*h3v;
    }

    int idx = j * BATCH + b;
    float c  = cst[idx];
    float iv = sigf(a0), fv = sigf(a1), gv = tanhf(a2), ov = sigf(a3);
    c = fv * c + iv * gv;
    cst[idx]  = c;
    hout[idx] = ov * tanhf(c);
}

// ---------------- fc + argmax ----------------
// Block (32 lanes = v, 8 ty = batch-groups of 8). Each thread: one v, 8 batches.
// Writes logits coalesced along v; argmax per batch via warp-reduce + atomicMax
// on packed (orderable-float, ~v) keys (order-independent, first-max on ties).
__global__ __launch_bounds__(256) void fc_kernel(
    const float* __restrict__ fcW, const float* __restrict__ fcb,
    float* __restrict__ outp, int ppo)
{
    const float* __restrict__ h = g_h1[ppo];
    int lane = threadIdx.x;
    int ty   = threadIdx.y;
    int v    = blockIdx.x * 32 + lane;
    int b0   = ty * 8;

    float acc[8];
#pragma unroll
    for (int i = 0; i < 8; i++) acc[i] = 0.f;

    const float4* w = reinterpret_cast<const float4*>(fcW + (size_t)v * HDIM);
#pragma unroll 4
    for (int k4 = 0; k4 < HDIM / 4; k4++) {
        float4 wv = w[k4];
        int k = k4 * 4;
#pragma unroll
        for (int kk = 0; kk < 4; kk++) {
            float wk = (kk == 0) ? wv.x : (kk == 1) ? wv.y : (kk == 2) ? wv.z : wv.w;
            const float4 hA = *reinterpret_cast<const float4*>(h + (k+kk)*BATCH + b0);
            const float4 hB = *reinterpret_cast<const float4*>(h + (k+kk)*BATCH + b0 + 4);
            acc[0] += wk * hA.x; acc[1] += wk * hA.y;
            acc[2] += wk * hA.z; acc[3] += wk * hA.w;
            acc[4] += wk * hB.x; acc[5] += wk * hB.y;
            acc[6] += wk * hB.z; acc[7] += wk * hB.w;
        }
    }

    float bias = fcb[v];
    float lg[8];
#pragma unroll
    for (int i = 0; i < 8; i++) {
        lg[i] = acc[i] + bias;
        outp[(size_t)(b0 + i) * VOC + v] = lg[i];
    }

#pragma unroll
    for (int i = 0; i < 8; i++) {
        unsigned u = __float_as_uint(lg[i]);
        u = (u & 0x80000000u) ? ~u : (u | 0x80000000u);
        unsigned long long key =
            ((unsigned long long)u << 32) |
            (unsigned long long)(0xFFFFFFFFu - (unsigned)v);
#pragma unroll
        for (int off = 16; off; off >>= 1) {
            unsigned long long o = __shfl_down_sync(0xffffffffu, key, off);
            key = (o > key) ? o : key;
        }
        if (lane == 0) atomicMax(&g_arg[b0 + i], key);
    }
}

// ---------------- host launch (graph-capturable: kernels only) ----------------
extern "C" void kernel_launch(void* const* d_in, const int* in_sizes, int n_in,
                              void* d_out, int out_size)
{
    // setup_inputs() dict order
    const int*   src       = (const int*)  d_in[0];
    const int*   target    = (const int*)  d_in[1];
    const int*   tfm       = (const int*)  d_in[2];
    const float* enc_embed = (const float*)d_in[3];
    const float* dec_embed = (const float*)d_in[4];
    const float* eWih0 = (const float*)d_in[5];
    const float* eWhh0 = (const float*)d_in[6];
    const float* ebih0 = (const float*)d_in[7];
    const float* ebhh0 = (const float*)d_in[8];
    const float* eWih1 = (const float*)d_in[9];
    const float* eWhh1 = (const float*)d_in[10];
    const float* ebih1 = (const float*)d_in[11];
    const float* ebhh1 = (const float*)d_in[12];
    const float* dWih0 = (const float*)d_in[13];
    const float* dWhh0 = (const float*)d_in[14];
    const float* dbih0 = (const float*)d_in[15];
    const float* dbhh0 = (const float*)d_in[16];
    const float* dWih1 = (const float*)d_in[17];
    const float* dWhh1 = (const float*)d_in[18];
    const float* dbih1 = (const float*)d_in[19];
    const float* dbhh1 = (const float*)d_in[20];
    const float* fcW   = (const float*)d_in[21];
    const float* fcb   = (const float*)d_in[22];
    float* out = (float*)d_out;

    dim3 lstmBlk(64, 4);
    dim3 fcBlk(32, 8);

    init_kernel<<<512, 256>>>(out);

    // ---- encoder ----
    for (int t = 0; t < SLEN; t++) {
        int ppo = (t & 1) ^ 1;
        lstm_step<EDIM, true, 0><<<128, lstmBlk>>>(
            eWih0, eWhh0, ebih0, ebhh0, enc_embed, src + t * BATCH,
            nullptr, nullptr, 0, 0, ppo, 0);
        lstm_step<HDIM, false, 1><<<128, lstmBlk>>>(
            eWih1, eWhh1, ebih1, ebhh1, nullptr, nullptr,
            nullptr, nullptr, 0, 0, ppo, 0);
    }

    // ---- decoder ----
    for (int s = 0; s < TLEN - 1; s++) {
        int ppo = (s & 1) ^ 1;
        lstm_step<EDIM, true, 0><<<128, lstmBlk>>>(
            dWih0, dWhh0, dbih0, dbhh0, dec_embed, nullptr,
            target, tfm, s, 1, ppo, 0);
        lstm_step<HDIM, false, 1><<<128, lstmBlk>>>(
            dWih1, dWhh1, dbih1, dbhh1, nullptr, nullptr,
            nullptr, nullptr, 0, 0, ppo, 1 /* reset argmax buffer */);
        fc_kernel<<<VOC / 32, fcBlk>>>(
            fcW, fcb, out + (size_t)(s + 1) * BATCH * VOC, ppo);
    }
}

// round 5
// speedup vs baseline: 3.5178x; 3.5178x over previous
#include <cuda_runtime.h>
#include <cuda_bf16.h>
#include <math.h>

// Problem constants
#define VOC   32000
#define EDIM  200
#define HDIM  512
#define SLEN  64
#define TLEN  64
#define BATCH 64
#define HB    (HDIM*BATCH)   // 32768

// ---------------- device scratch (static, no runtime allocation) ----------------
__device__ float g_h0[2][HB];
__device__ float g_h1[2][HB];
__device__ float g_c0[HB];
__device__ float g_c1[HB];
__device__ unsigned long long g_arg[BATCH];
__device__ float g_WT[(size_t)HDIM * VOC];   // fc weights transposed [k][v], 64MB

__device__ __forceinline__ float sigf(float x) { return 1.0f / (1.0f + expf(-x)); }

// ---------------- init: zero states + out[0] ----------------
__global__ void init_kernel(float* __restrict__ out)
{
    int idx = blockIdx.x * blockDim.x + threadIdx.x;
    if (idx < HB) {
        g_h0[0][idx] = 0.f;
        g_h1[0][idx] = 0.f;
        g_c0[idx]    = 0.f;
        g_c1[idx]    = 0.f;
    }
    for (int i = idx; i < BATCH * VOC; i += gridDim.x * blockDim.x)
        out[i] = 0.f;
}

// ---------------- transpose fc weights: [V][H] -> [H][V] ----------------
__global__ __launch_bounds__(256) void transpose_fc(const float* __restrict__ W)
{
    __shared__ float t[32][33];
    int v0 = blockIdx.x * 32, k0 = blockIdx.y * 32;
    int tx = threadIdx.x, ty = threadIdx.y;
#pragma unroll
    for (int i = 0; i < 32; i += 8)
        t[ty + i][tx] = W[(size_t)(v0 + ty + i) * HDIM + k0 + tx];
    __syncthreads();
#pragma unroll
    for (int i = 0; i < 32; i += 8)
        g_WT[(size_t)(k0 + ty + i) * VOC + v0 + tx] = t[tx][ty + i];
}

// ---------------- one LSTM layer, one step ----------------
// grid = 512 (j), block = (64 batch, 4 K-slices). Each thread accumulates the 4
// gate dots of row-quadruple {j, H+j, 2H+j, 3H+j} for its (b) over its K-slice,
// then a smem reduction + single finalize applies activations and updates c,h.
template <int KX, bool GATHER, int LAYER>
__global__ __launch_bounds__(256, 4) void lstm_step2(
    const float* __restrict__ Wih, const float* __restrict__ Whh,
    const float* __restrict__ bih, const float* __restrict__ bhh,
    const float* __restrict__ emb,   // GATHER: embedding table [V][KX]
    const int*   __restrict__ toks,  // encoder: src + t*B
    const int*   __restrict__ target,
    const int*   __restrict__ tfm,
    int step, int dec, int ppo, int resetArg)
{
    const int b = threadIdx.x;   // 0..63
    const int s = threadIdx.y;   // 0..3  (K-slice)
    const int j = blockIdx.x;    // 0..511

    if (LAYER == 1 && resetArg && blockIdx.x == 0 && s == 0)
        g_arg[b] = 0ull;   // consumed by the fc launched after this kernel

    const float* __restrict__ hprev = (LAYER == 0) ? g_h0[ppo ^ 1] : g_h1[ppo ^ 1];

    float a0 = 0.f, a1 = 0.f, a2 = 0.f, a3 = 0.f;

    // ---- input part ----
    if constexpr (GATHER) {
        // KX = 200 -> 50 elems per slice (float2 granularity for alignment)
        int tok;
        if (!dec) {
            tok = toks[b];
        } else {
            if (step == 0) {
                tok = target[b];
            } else if (tfm[step] > 0) {
                tok = target[step * BATCH + b];
            } else {
                unsigned long long k = g_arg[b];
                tok = (int)(0xFFFFFFFFu - (unsigned)(k & 0xFFFFFFFFull));
            }
        }
        const float2* xr = reinterpret_cast<const float2*>(emb + (size_t)tok * KX) + 25 * s;
        const float2* w0 = reinterpret_cast<const float2*>(Wih + (size_t)j          * KX) + 25 * s;
        const float2* w1 = reinterpret_cast<const float2*>(Wih + (size_t)(HDIM   + j) * KX) + 25 * s;
        const float2* w2 = reinterpret_cast<const float2*>(Wih + (size_t)(2*HDIM + j) * KX) + 25 * s;
        const float2* w3 = reinterpret_cast<const float2*>(Wih + (size_t)(3*HDIM + j) * KX) + 25 * s;
#pragma unroll 5
        for (int k = 0; k < 25; k++) {
            float2 xv = xr[k];
            float2 A0 = w0[k], A1 = w1[k], A2 = w2[k], A3 = w3[k];
            a0 += A0.x * xv.x + A0.y * xv.y;
            a1 += A1.x * xv.x + A1.y * xv.y;
            a2 += A2.x * xv.x + A2.y * xv.y;
            a3 += A3.x * xv.x + A3.y * xv.y;
        }
    } else {
        // KX = 512, input = current h0 ; 128 elems per slice
        const float* __restrict__ xin = g_h0[ppo];
        const float4* w0 = reinterpret_cast<const float4*>(Wih + (size_t)j          * KX) + 32 * s;
        const float4* w1 = reinterpret_cast<const float4*>(Wih + (size_t)(HDIM   + j) * KX) + 32 * s;
        const float4* w2 = reinterpret_cast<const float4*>(Wih + (size_t)(2*HDIM + j) * KX) + 32 * s;
        const float4* w3 = reinterpret_cast<const float4*>(Wih + (size_t)(3*HDIM + j) * KX) + 32 * s;
        const int kb = 128 * s;
#pragma unroll 8
        for (int kk = 0; kk < 32; kk++) {
            const int k = kb + kk * 4;
            float x0 = xin[(k+0)*BATCH + b];
            float x1 = xin[(k+1)*BATCH + b];
            float x2 = xin[(k+2)*BATCH + b];
            float x3 = xin[(k+3)*BATCH + b];
            float4 A0 = w0[kk], A1 = w1[kk], A2 = w2[kk], A3 = w3[kk];
            a0 += A0.x*x0 + A0.y*x1 + A0.z*x2 + A0.w*x3;
            a1 += A1.x*x0 + A1.y*x1 + A1.z*x2 + A1.w*x3;
            a2 += A2.x*x0 + A2.y*x1 + A2.z*x2 + A2.w*x3;
            a3 += A3.x*x0 + A3.y*x1 + A3.z*x2 + A3.w*x3;
        }
    }

    // ---- recurrent part (K = 512, 128 per slice) ----
    {
        const float4* u0 = reinterpret_cast<const float4*>(Whh + (size_t)j          * HDIM) + 32 * s;
        const float4* u1 = reinterpret_cast<const float4*>(Whh + (size_t)(HDIM   + j) * HDIM) + 32 * s;
        const float4* u2 = reinterpret_cast<const float4*>(Whh + (size_t)(2*HDIM + j) * HDIM) + 32 * s;
        const float4* u3 = reinterpret_cast<const float4*>(Whh + (size_t)(3*HDIM + j) * HDIM) + 32 * s;
        const int kb = 128 * s;
#pragma unroll 8
        for (int kk = 0; kk < 32; kk++) {
            const int k = kb + kk * 4;
            float h0v = hprev[(k+0)*BATCH + b];
            float h1v = hprev[(k+1)*BATCH + b];
            float h2v = hprev[(k+2)*BATCH + b];
            float h3v = hprev[(k+3)*BATCH + b];
            float4 U0 = u0[kk], U1 = u1[kk], U2 = u2[kk], U3 = u3[kk];
            a0 += U0.x*h0v + U0.y*h1v + U0.z*h2v + U0.w*h3v;
            a1 += U1.x*h0v + U1.y*h1v + U1.z*h2v + U1.w*h3v;
            a2 += U2.x*h0v + U2.y*h1v + U2.z*h2v + U2.w*h3v;
            a3 += U3.x*h0v + U3.y*h1v + U3.z*h2v + U3.w*h3v;
        }
    }

    // ---- reduce slices, finalize ----
    __shared__ float sg[4][4][64];
    sg[0][s][b] = a0; sg[1][s][b] = a1; sg[2][s][b] = a2; sg[3][s][b] = a3;
    __syncthreads();

    if (threadIdx.y == 0) {
        const int bb = b;
        float g0 = bih[j]          + bhh[j]          + sg[0][0][bb] + sg[0][1][bb] + sg[0][2][bb] + sg[0][3][bb];
        float g1 = bih[HDIM   + j] + bhh[HDIM   + j] + sg[1][0][bb] + sg[1][1][bb] + sg[1][2][bb] + sg[1][3][bb];
        float g2 = bih[2*HDIM + j] + bhh[2*HDIM + j] + sg[2][0][bb] + sg[2][1][bb] + sg[2][2][bb] + sg[2][3][bb];
        float g3 = bih[3*HDIM + j] + bhh[3*HDIM + j] + sg[3][0][bb] + sg[3][1][bb] + sg[3][2][bb] + sg[3][3][bb];

        float* __restrict__ cst  = (LAYER == 0) ? g_c0      : g_c1;
        float* __restrict__ hout = (LAYER == 0) ? g_h0[ppo] : g_h1[ppo];
        const int idx = j * BATCH + bb;
        float c  = cst[idx];
        float iv = sigf(g0), fv = sigf(g1), gv = tanhf(g2), ov = sigf(g3);
        c = fv * c + iv * gv;
        cst[idx]  = c;
        hout[idx] = ov * tanhf(c);
    }
}

// ---------------- fc + argmax (transposed weights) ----------------
// grid = 250, block (32 v4-lanes, 8 b-groups). Thread: 4 consecutive v x 8 b.
// g_WT loads coalesced along v; h broadcast across the warp.
__global__ __launch_bounds__(256, 2) void fc2(
    const float* __restrict__ fcb, float* __restrict__ outp, int ppo)
{
    const float* __restrict__ h = g_h1[ppo];
    const int lane = threadIdx.x;             // 0..31
    const int ty   = threadIdx.y;             // 0..7
    const int v4   = blockIdx.x * 32 + lane;  // 0..7999
    const int v    = v4 * 4;
    const int b0   = ty * 8;

    float acc[4][8];
#pragma unroll
    for (int i = 0; i < 4; i++)
#pragma unroll
        for (int jj = 0; jj < 8; jj++) acc[i][jj] = 0.f;

    const float4* __restrict__ wt = reinterpret_cast<const float4*>(g_WT);
#pragma unroll 4
    for (int k = 0; k < HDIM; k++) {
        float4 w  = wt[(size_t)k * (VOC/4) + v4];
        float4 hA = *reinterpret_cast<const float4*>(h + k*BATCH + b0);
        float4 hB = *reinterpret_cast<const float4*>(h + k*BATCH + b0 + 4);
        float hv[8] = {hA.x, hA.y, hA.z, hA.w, hB.x, hB.y, hB.z, hB.w};
#pragma unroll
        for (int jj = 0; jj < 8; jj++) {
            acc[0][jj] += w.x * hv[jj];
            acc[1][jj] += w.y * hv[jj];
            acc[2][jj] += w.z * hv[jj];
            acc[3][jj] += w.w * hv[jj];
        }
    }

    float4 bias = *reinterpret_cast<const float4*>(fcb + v);
    float lg[4][8];
#pragma unroll
    for (int jj = 0; jj < 8; jj++) {
        lg[0][jj] = acc[0][jj] + bias.x;
        lg[1][jj] = acc[1][jj] + bias.y;
        lg[2][jj] = acc[2][jj] + bias.z;
        lg[3][jj] = acc[3][jj] + bias.w;
        float4 o = make_float4(lg[0][jj], lg[1][jj], lg[2][jj], lg[3][jj]);
        *reinterpret_cast<float4*>(outp + (size_t)(b0 + jj) * VOC + v) = o;
    }

    // argmax: per (thread,b) pick best of its 4 v (strict > keeps lowest v),
    // then warp-reduce packed keys, lane0 -> atomicMax.
#pragma unroll
    for (int jj = 0; jj < 8; jj++) {
        float m = lg[0][jj]; int vi = 0;
        if (lg[1][jj] > m) { m = lg[1][jj]; vi = 1; }
        if (lg[2][jj] > m) { m = lg[2][jj]; vi = 2; }
        if (lg[3][jj] > m) { m = lg[3][jj]; vi = 3; }
        unsigned u = __float_as_uint(m);
        u = (u & 0x80000000u) ? ~u : (u | 0x80000000u);
        unsigned long long key =
            ((unsigned long long)u << 32) |
            (unsigned long long)(0xFFFFFFFFu - (unsigned)(v + vi));
#pragma unroll
        for (int off = 16; off; off >>= 1) {
            unsigned long long o = __shfl_down_sync(0xffffffffu, key, off);
            key = (o > key) ? o : key;
        }
        if (lane == 0) atomicMax(&g_arg[b0 + jj], key);
    }
}

// ---------------- host launch (graph-capturable: kernels only) ----------------
extern "C" void kernel_launch(void* const* d_in, const int* in_sizes, int n_in,
                              void* d_out, int out_size)
{
    const int*   src       = (const int*)  d_in[0];
    const int*   target    = (const int*)  d_in[1];
    const int*   tfm       = (const int*)  d_in[2];
    const float* enc_embed = (const float*)d_in[3];
    const float* dec_embed = (const float*)d_in[4];
    const float* eWih0 = (const float*)d_in[5];
    const float* eWhh0 = (const float*)d_in[6];
    const float* ebih0 = (const float*)d_in[7];
    const float* ebhh0 = (const float*)d_in[8];
    const float* eWih1 = (const float*)d_in[9];
    const float* eWhh1 = (const float*)d_in[10];
    const float* ebih1 = (const float*)d_in[11];
    const float* ebhh1 = (const float*)d_in[12];
    const float* dWih0 = (const float*)d_in[13];
    const float* dWhh0 = (const float*)d_in[14];
    const float* dbih0 = (const float*)d_in[15];
    const float* dbhh0 = (const float*)d_in[16];
    const float* dWih1 = (const float*)d_in[17];
    const float* dWhh1 = (const float*)d_in[18];
    const float* dbih1 = (const float*)d_in[19];
    const float* dbhh1 = (const float*)d_in[20];
    const float* fcW   = (const float*)d_in[21];
    const float* fcb   = (const float*)d_in[22];
    float* out = (float*)d_out;

    dim3 lstmBlk(64, 4);
    dim3 fcBlk(32, 8);

    init_kernel<<<512, 256>>>(out);
    transpose_fc<<<dim3(VOC/32, HDIM/32), dim3(32, 8)>>>(fcW);

    // ---- encoder ----
    for (int t = 0; t < SLEN; t++) {
        int ppo = (t & 1) ^ 1;
        lstm_step2<EDIM, true, 0><<<512, lstmBlk>>>(
            eWih0, eWhh0, ebih0, ebhh0, enc_embed, src + t * BATCH,
            nullptr, nullptr, 0, 0, ppo, 0);
        lstm_step2<HDIM, false, 1><<<512, lstmBlk>>>(
            eWih1, eWhh1, ebih1, ebhh1, nullptr, nullptr,
            nullptr, nullptr, 0, 0, ppo, 0);
    }

    // ---- decoder ----
    for (int s = 0; s < TLEN - 1; s++) {
        int ppo = (s & 1) ^ 1;
        lstm_step2<EDIM, true, 0><<<512, lstmBlk>>>(
            dWih0, dWhh0, dbih0, dbhh0, dec_embed, nullptr,
            target, tfm, s, 1, ppo, 0);
        lstm_step2<HDIM, false, 1><<<512, lstmBlk>>>(
            dWih1, dWhh1, dbih1, dbhh1, nullptr, nullptr,
            nullptr, nullptr, 0, 0, ppo, 1 /* reset argmax */);
        fc2<<<VOC/128, fcBlk>>>(fcb, out + (size_t)(s + 1) * BATCH * VOC, ppo);
    }
}